// round 7
// baseline (speedup 1.0000x reference)
#include <cuda_runtime.h>
#include <math.h>

#define BATCH  4096
#define NMODES 512
#define NLU    128
#define NB     8
#define JB     16

// ---------------- scratch (static device globals; no allocation) ----------------
__device__ int   g_idx[BATCH * 256];
__device__ float g_logj[BATCH];
__device__ float g_sign[BATCH * 2];
__device__ float g_labs[BATCH * 2];

// ---------------- kernel 1: occupied-index extraction ---------------------------
__global__ void idx_kernel(const int* __restrict__ n) {
    int b = blockIdx.x;
    int t = threadIdx.x;
    __shared__ int wcu[8], wcd[8];
    int vu = n[b * NMODES + t];
    int vd = n[b * NMODES + 256 + t];
    unsigned mu = __ballot_sync(0xffffffffu, vu != 0);
    unsigned md = __ballot_sync(0xffffffffu, vd != 0);
    int lane = t & 31, w = t >> 5;
    if (lane == 0) { wcu[w] = __popc(mu); wcd[w] = __popc(md); }
    __syncthreads();
    int bu = 0, bd = 0;
    for (int i = 0; i < w; i++) { bu += wcu[i]; bd += wcd[i]; }
    unsigned lt = (1u << lane) - 1u;
    if (vu) g_idx[b * 256 + bu + __popc(mu & lt)] = t;
    if (vd) g_idx[b * 256 + 128 + bd + __popc(md & lt)] = t;
}

// ---------------- kernel 2: Jastrow ---------------------------------------------
__global__ __launch_bounds__(256) void jastrow_kernel(const int* __restrict__ n,
                                                      const float* __restrict__ v) {
    int b0 = blockIdx.x * JB;
    __shared__ float sn[JB][NMODES];
    __shared__ float spart[JB][8];
    int tid = threadIdx.x;
    for (int x = tid; x < JB * NMODES; x += 256)
        sn[x >> 9][x & 511] = (float)n[b0 * NMODES + x];
    __syncthreads();

    int j0 = tid * 2;
    float acc0[JB], acc1[JB];
#pragma unroll
    for (int bb = 0; bb < JB; bb++) { acc0[bb] = 0.f; acc1[bb] = 0.f; }

    for (int i = 0; i < NMODES; i++) {
        float2 vv = *reinterpret_cast<const float2*>(v + (size_t)i * NMODES + j0);
#pragma unroll
        for (int bb = 0; bb < JB; bb++) {
            float f = sn[bb][i];
            acc0[bb] += f * vv.x;
            acc1[bb] += f * vv.y;
        }
    }

    int lane = tid & 31, wrp = tid >> 5;
#pragma unroll
    for (int bb = 0; bb < JB; bb++) {
        float s = acc0[bb] * sn[bb][j0] + acc1[bb] * sn[bb][j0 + 1];
#pragma unroll
        for (int off = 16; off > 0; off >>= 1)
            s += __shfl_down_sync(0xffffffffu, s, off);
        if (lane == 0) spart[bb][wrp] = s;
    }
    __syncthreads();
    if (tid < JB) {
        float s = 0.f;
#pragma unroll
        for (int w = 0; w < 8; w++) s += spart[tid][w];
        g_logj[b0 + tid] = -0.5f * s;
    }
}

// ---------------- dummy kernel (ncu slot alignment: puts lu at -s 5) ------------
__global__ void pad_kernel() {}

// ---------------- kernel 3: dual-matrix lookahead LU -> slogdet -----------------
extern __shared__ float As[];
#define MSTRIDE (NLU * 129)
#define A(g, i, j) As[(g) * MSTRIDE + (i) * 129 + (j)]

__device__ __forceinline__ int apply_sigma(int x, const int* pl, int kprev) {
#pragma unroll
    for (int k = NB - 1; k >= 0; k--) {
        int kr = kprev + k, qp = pl[k];
        x = (x == kr) ? qp : ((x == qp) ? kr : x);
    }
    return x;
}

__global__ __launch_bounds__(512, 1) void lu_kernel(const float* __restrict__ phi_up,
                                                    const float* __restrict__ phi_dn) {
    int b   = blockIdx.x;
    int tid = threadIdx.x;
    int g   = tid >> 8;              // matrix/group: 0=up, 1=dn
    int gt  = tid & 255;             // thread id within group
    int gwid = gt >> 5;              // warp id within group (0..7)
    int lane = tid & 31;

    const float* __restrict__ phi = g ? phi_dn : phi_up;
    const int*   __restrict__ idx = g_idx + b * 256 + g * 128;

    __shared__ int   s_pl[2][2][NB];   // [mat][parity][k]
    __shared__ float s_u[2][NB * NB];

    // gather: each group loads its matrix (coalesced)
    {
        int c = gt & 127, rh = gt >> 7;
        for (int it = 0; it < 64; it++) {
            int r = (it << 1) + rh;
            A(g, r, c) = phi[idx[r] * NLU + c];
        }
    }
    __syncthreads();

    float t_logabs = 0.f;
    float t_sign   = 1.f;

    for (int k0 = 0; k0 < NLU; k0 += NB) {
        int kprev = k0 - NB;
        int par   = (k0 >> 3) & 1;
        bool first = (k0 == 0);

        if (gwid == 0) {
            // ================= panel warp: prep + factor cols [k0,k0+8) ==========
            int m0 = NLU - k0;
            int pl[NB];
            if (!first) {
#pragma unroll
                for (int k = 0; k < NB; k++) pl[k] = s_pl[g][par ^ 1][k];
            }

            // gather strip rows (sigma-mapped sources) into registers
            float p[4][NB];
            int   pos[4];
            bool  done[4];
#pragma unroll
            for (int s = 0; s < 4; s++) {
                int rr = lane + 32 * s;
                bool valid = (rr < m0);
                int r = k0 + rr;
                int src = r;
                if (!first && valid) src = apply_sigma(r, pl, kprev);
#pragma unroll
                for (int c = 0; c < NB; c++)
                    p[s][c] = valid ? A(g, src, k0 + c) : 0.f;
                pos[s]  = r;
                done[s] = !valid;
            }

            if (!first) {
                // TRSM of this strip's U12 block (lanes 0..7, one column each)
                if (lane < NB) {
                    float u[NB];
#pragma unroll
                    for (int rr = 0; rr < NB; rr++) {
                        int sr = apply_sigma(kprev + rr, pl, kprev);
                        float x = A(g, sr, k0 + lane);
#pragma unroll
                        for (int t = 0; t < NB; t++)
                            if (t < rr) x -= A(g, kprev + rr, kprev + t) * u[t];
                        u[rr] = x;
                    }
#pragma unroll
                    for (int t = 0; t < NB; t++) s_u[g][t * NB + lane] = u[t];
                }
                __syncwarp();

                // pre-GEMM: p -= L21(prev panel) * U12
#pragma unroll
                for (int t = 0; t < NB; t++) {
                    float ub[NB];
#pragma unroll
                    for (int c = 0; c < NB; c++) ub[c] = s_u[g][t * NB + c];
#pragma unroll
                    for (int s = 0; s < 4; s++) {
                        if (!done[s]) {
                            float lt = A(g, k0 + lane + 32 * s, kprev + t);
#pragma unroll
                            for (int c = 0; c < NB; c++)
                                p[s][c] -= lt * ub[c];
                        }
                    }
                }
            }

            // register factorization with virtual pivoting
            float ur[NB];
#pragma unroll
            for (int kk = 0; kk < NB; kk++) {
                int kabs = k0 + kk;
                unsigned best = 0u;
#pragma unroll
                for (int s = 0; s < 4; s++) {
                    if (!done[s]) {
                        unsigned ab  = __float_as_uint(p[s][kk]) & 0x7FFFFFFFu;
                        unsigned key = (ab & 0xFFFFFF80u) | (unsigned)(lane + 32 * s);
                        if (key > best) best = key;
                    }
                }
                best = __reduce_max_sync(0xffffffffu, best);
                int prr = (int)(best & 0x7Fu);     // relative row
                int psl = prr >> 5, pln = prr & 31;

#pragma unroll
                for (int c = 0; c < NB; c++) {
                    float tv = (psl == 0) ? p[0][c] : (psl == 1) ? p[1][c]
                              : (psl == 2) ? p[2][c] : p[3][c];
                    ur[c] = __shfl_sync(0xffffffffu, tv, pln);
                }
                int tq = (psl == 0) ? pos[0] : (psl == 1) ? pos[1]
                        : (psl == 2) ? pos[2] : pos[3];
                int qp = __shfl_sync(0xffffffffu, tq, pln);

                float piv = ur[kk];
                t_logabs += __logf(fabsf(piv));
                if (piv < 0.f)  t_sign = -t_sign;
                if (qp != kabs) t_sign = -t_sign;
                if (lane == 0)  s_pl[g][par][kk] = qp;

#pragma unroll
                for (int s = 0; s < 4; s++) {
                    int rr = lane + 32 * s;
                    if (rr == prr) { pos[s] = kabs; done[s] = true; }
                    else if (!done[s] && pos[s] == kabs) pos[s] = qp;
                }

                float inv = __fdividef(1.0f, piv);
#pragma unroll
                for (int s = 0; s < 4; s++) {
                    if (!done[s]) {
                        float mll = p[s][kk] * inv;
                        p[s][kk] = mll;
#pragma unroll
                        for (int c = kk + 1; c < NB; c++)
                            p[s][c] -= mll * ur[c];
                    }
                }
            }
            __syncwarp();

            // writeback to final (post-swap) positions
#pragma unroll
            for (int s = 0; s < 4; s++) {
                if (lane + 32 * s < m0) {
#pragma unroll
                    for (int c = 0; c < NB; c++)
                        A(g, pos[s], k0 + c) = p[s][c];
                }
            }
        } else if (!first) {
            // ========== update warps: prev panel's trailing cols [k0+8,128) ======
            int q  = gt - 32;              // 0..223
            int cb = k0 + NB;
            int pl[NB];
#pragma unroll
            for (int k = 0; k < NB; k++) pl[k] = s_pl[g][par ^ 1][k];

            // fused: sigma swaps + TRSM per column
            for (int j = cb + q; j < NLU; j += 224) {
#pragma unroll
                for (int k = 0; k < NB; k++) {
                    int qp = pl[k], kr = kprev + k;
                    if (qp != kr) {
                        float a0 = A(g, kr, j), b0 = A(g, qp, j);
                        A(g, kr, j) = b0; A(g, qp, j) = a0;
                    }
                }
                float u[NB];
#pragma unroll
                for (int rr = 0; rr < NB; rr++) {
                    float x = A(g, kprev + rr, j);
#pragma unroll
                    for (int t = 0; t < NB; t++)
                        if (t < rr) x -= A(g, kprev + rr, kprev + t) * u[t];
                    u[rr] = x;
                    A(g, kprev + rr, j) = x;
                }
            }
            if (g == 0) asm volatile("bar.sync 1, 224;" ::: "memory");
            else        asm volatile("bar.sync 2, 224;" ::: "memory");

            // GEMM: rows [k0,128) x cols [k0+8,128) -= L21 * U12  (k-chunk 8)
            int mrows = NLU - k0;
            int ncols = NLU - cb;
            int tx = q & 15, ty = q >> 4;  // ty 0..13

            for (int sa = 0; sa < mrows; sa += 56)
            for (int sb = 0; sb < ncols; sb += 64) {
                int ia[4], jb[4];
                bool rv[4], cv[4];
#pragma unroll
                for (int a = 0; a < 4; a++) {
                    int ro = sa + ty + 14 * a;
                    rv[a] = (ro < mrows); ia[a] = rv[a] ? (k0 + ro) : k0;
                    int co = sb + tx + 16 * a;
                    cv[a] = (co < ncols); jb[a] = cv[a] ? (cb + co) : cb;
                }
                float acc[4][4];
#pragma unroll
                for (int a = 0; a < 4; a++)
#pragma unroll
                for (int c = 0; c < 4; c++)
                    acc[a][c] = A(g, ia[a], jb[c]);
#pragma unroll
                for (int t = 0; t < NB; t++) {
                    float la[4], lb[4];
#pragma unroll
                    for (int a = 0; a < 4; a++) {
                        la[a] = A(g, ia[a], kprev + t);
                        lb[a] = A(g, kprev + t, jb[a]);
                    }
#pragma unroll
                    for (int a = 0; a < 4; a++)
#pragma unroll
                    for (int c = 0; c < 4; c++)
                        acc[a][c] -= la[a] * lb[c];
                }
#pragma unroll
                for (int a = 0; a < 4; a++)
#pragma unroll
                for (int c = 0; c < 4; c++)
                    if (rv[a] && cv[c]) A(g, ia[a], jb[c]) = acc[a][c];
            }
        }
        __syncthreads();
    }

    if (gwid == 0 && lane == 0) {
        g_sign[2 * b + g] = t_sign;
        g_labs[2 * b + g] = t_logabs;
    }
}

// ---------------- kernel 4: combine ---------------------------------------------
__global__ void combine_kernel(float* __restrict__ out) {
    int b = blockIdx.x * 256 + threadIdx.x;
    if (b < BATCH) {
        out[b]         = g_sign[2 * b] * g_sign[2 * b + 1];
        out[BATCH + b] = g_logj[b] + g_labs[2 * b] + g_labs[2 * b + 1];
    }
}

// ---------------- launch ---------------------------------------------------------
extern "C" void kernel_launch(void* const* d_in, const int* in_sizes, int n_in,
                              void* d_out, int out_size) {
    const int*   n      = (const int*)d_in[0];
    const float* phi_up = (const float*)d_in[1];
    const float* phi_dn = (const float*)d_in[2];
    const float* v      = (const float*)d_in[3];
    float* out = (float*)d_out;

    const int LU_SMEM = 2 * NLU * 129 * (int)sizeof(float);   // 132096 B
    cudaFuncSetAttribute(lu_kernel, cudaFuncAttributeMaxDynamicSharedMemorySize, LU_SMEM);

    idx_kernel<<<BATCH, 256>>>(n);
    jastrow_kernel<<<BATCH / JB, 256>>>(n, v);
    pad_kernel<<<1, 32>>>();                       // aligns lu_kernel to ncu -s 5
    lu_kernel<<<BATCH, 512, LU_SMEM>>>(phi_up, phi_dn);
    combine_kernel<<<(BATCH + 255) / 256, 256>>>(out);
}

// round 8
// speedup vs baseline: 1.4764x; 1.4764x over previous
#include <cuda_runtime.h>
#include <math.h>

#define BATCH  4096
#define NMODES 512
#define NLU    128
#define NB     8
#define JB     16

// ---------------- scratch (static device globals; no allocation) ----------------
__device__ int   g_idx[BATCH * 256];
__device__ float g_logj[BATCH];
__device__ float g_sign[BATCH * 2];
__device__ float g_labs[BATCH * 2];

// ---------------- kernel 1: occupied-index extraction ---------------------------
__global__ void idx_kernel(const int* __restrict__ n) {
    int b = blockIdx.x;
    int t = threadIdx.x;
    __shared__ int wcu[8], wcd[8];
    int vu = n[b * NMODES + t];
    int vd = n[b * NMODES + 256 + t];
    unsigned mu = __ballot_sync(0xffffffffu, vu != 0);
    unsigned md = __ballot_sync(0xffffffffu, vd != 0);
    int lane = t & 31, w = t >> 5;
    if (lane == 0) { wcu[w] = __popc(mu); wcd[w] = __popc(md); }
    __syncthreads();
    int bu = 0, bd = 0;
    for (int i = 0; i < w; i++) { bu += wcu[i]; bd += wcd[i]; }
    unsigned lt = (1u << lane) - 1u;
    if (vu) g_idx[b * 256 + bu + __popc(mu & lt)] = t;
    if (vd) g_idx[b * 256 + 128 + bd + __popc(md & lt)] = t;
}

// ---------------- kernel 2: Jastrow ---------------------------------------------
__global__ __launch_bounds__(256) void jastrow_kernel(const int* __restrict__ n,
                                                      const float* __restrict__ v) {
    int b0 = blockIdx.x * JB;
    __shared__ float sn[JB][NMODES];
    __shared__ float spart[JB][8];
    int tid = threadIdx.x;
    for (int x = tid; x < JB * NMODES; x += 256)
        sn[x >> 9][x & 511] = (float)n[b0 * NMODES + x];
    __syncthreads();

    int j0 = tid * 2;
    float acc0[JB], acc1[JB];
#pragma unroll
    for (int bb = 0; bb < JB; bb++) { acc0[bb] = 0.f; acc1[bb] = 0.f; }

    for (int i = 0; i < NMODES; i++) {
        float2 vv = *reinterpret_cast<const float2*>(v + (size_t)i * NMODES + j0);
#pragma unroll
        for (int bb = 0; bb < JB; bb++) {
            float f = sn[bb][i];
            acc0[bb] += f * vv.x;
            acc1[bb] += f * vv.y;
        }
    }

    int lane = tid & 31, wrp = tid >> 5;
#pragma unroll
    for (int bb = 0; bb < JB; bb++) {
        float s = acc0[bb] * sn[bb][j0] + acc1[bb] * sn[bb][j0 + 1];
#pragma unroll
        for (int off = 16; off > 0; off >>= 1)
            s += __shfl_down_sync(0xffffffffu, s, off);
        if (lane == 0) spart[bb][wrp] = s;
    }
    __syncthreads();
    if (tid < JB) {
        float s = 0.f;
#pragma unroll
        for (int w = 0; w < 8; w++) s += spart[tid][w];
        g_logj[b0 + tid] = -0.5f * s;
    }
}

// ---------------- dummy kernel (ncu slot alignment: keeps lu at -s 5) -----------
__global__ void pad_kernel() {}

// ---------------- kernel 3: blocked LU (register panel) -> slogdet --------------
extern __shared__ float As[];
#define A(i, j) As[(i) * 129 + (j)]

// Adaptive trailing-update tile: NA row-groups of 16 (exactly ceil(rem/16)),
// 4 col-groups of 16. Only the tail row/col groups carry runtime guards.
template<int NA>
__device__ __forceinline__ void gemm_tile(int k0, int rb, int sa, int sb, int m2,
                                          int tx, int ty) {
    int ia[NA], jb[4];
    bool rv[NA], cv[4];
#pragma unroll
    for (int a = 0; a < NA; a++) {
        int ro = sa + ty + 16 * a;
        rv[a] = (ro < m2);
        ia[a] = rv[a] ? (rb + ro) : rb;
    }
#pragma unroll
    for (int c = 0; c < 4; c++) {
        int co = sb + tx + 16 * c;
        cv[c] = (co < m2);
        jb[c] = cv[c] ? (rb + co) : rb;
    }
    float acc[NA][4];
#pragma unroll
    for (int a = 0; a < NA; a++)
#pragma unroll
    for (int c = 0; c < 4; c++)
        acc[a][c] = A(ia[a], jb[c]);
#pragma unroll
    for (int t = 0; t < NB; t++) {
        float la[NA], lb[4];
#pragma unroll
        for (int a = 0; a < NA; a++) la[a] = A(ia[a], k0 + t);
#pragma unroll
        for (int c = 0; c < 4; c++)  lb[c] = A(k0 + t, jb[c]);
#pragma unroll
        for (int a = 0; a < NA; a++)
#pragma unroll
        for (int c = 0; c < 4; c++)
            acc[a][c] -= la[a] * lb[c];
    }
#pragma unroll
    for (int a = 0; a < NA; a++)
#pragma unroll
    for (int c = 0; c < 4; c++)
        if (rv[a] && cv[c]) A(ia[a], jb[c]) = acc[a][c];
}

__global__ __launch_bounds__(256, 3) void lu_kernel(const float* __restrict__ phi_up,
                                                    const float* __restrict__ phi_dn) {
    int cta  = blockIdx.x;
    int b    = cta >> 1;
    int spin = cta & 1;
    const float* __restrict__ phi = spin ? phi_dn : phi_up;
    const int*   __restrict__ idx = g_idx + b * 256 + spin * 128;

    __shared__ int s_pivlist[NB];

    int tid  = threadIdx.x;
    int lane = tid & 31;

    // gather M = phi[idx] into smem (coalesced)
    {
        int c = tid & 127, rh = tid >> 7;
        for (int it = 0; it < 64; it++) {
            int r = (it << 1) + rh;
            A(r, c) = phi[idx[r] * NLU + c];
        }
    }

    float t_logabs = 0.f;
    float t_sign   = 1.f;

    int tx = tid & 15, ty = tid >> 4;

    for (int k0 = 0; k0 < NLU; k0 += NB) {
        __syncthreads();   // trailing matrix (incl. this panel) up to date

        // ===== single-warp REGISTER panel factorization (warp 0) =================
        if (tid < 32) {
            float p[4][NB];
            int   pos[4];
            bool  done[4];
#pragma unroll
            for (int s = 0; s < 4; s++) {
                int r = lane + 32 * s;
                done[s] = (r < k0);
#pragma unroll
                for (int c = 0; c < NB; c++)
                    p[s][c] = done[s] ? 0.f : A(r, k0 + c);
                pos[s] = r;
            }
            float ur[NB];
#pragma unroll
            for (int kk = 0; kk < NB; kk++) {
                int kabs = k0 + kk;
                unsigned best = 0u;
#pragma unroll
                for (int s = 0; s < 4; s++) {
                    if (!done[s]) {
                        unsigned ab  = __float_as_uint(p[s][kk]) & 0x7FFFFFFFu;
                        unsigned key = (ab & 0xFFFFFF80u) | (unsigned)(lane + 32 * s);
                        if (key > best) best = key;
                    }
                }
                best = __reduce_max_sync(0xffffffffu, best);
                int prr = (int)(best & 0x7Fu);
                int psl = prr >> 5, pln = prr & 31;
#pragma unroll
                for (int c = 0; c < NB; c++) {
                    float tv = (psl == 0) ? p[0][c] : (psl == 1) ? p[1][c]
                              : (psl == 2) ? p[2][c] : p[3][c];
                    ur[c] = __shfl_sync(0xffffffffu, tv, pln);
                }
                int tq = (psl == 0) ? pos[0] : (psl == 1) ? pos[1]
                        : (psl == 2) ? pos[2] : pos[3];
                int qp = __shfl_sync(0xffffffffu, tq, pln);

                float piv = ur[kk];
                t_logabs += __logf(fabsf(piv));
                if (piv < 0.f)  t_sign = -t_sign;
                if (qp != kabs) t_sign = -t_sign;
                if (lane == 0)  s_pivlist[kk] = qp;

#pragma unroll
                for (int s = 0; s < 4; s++) {
                    int r = lane + 32 * s;
                    if (r == prr) { pos[s] = kabs; done[s] = true; }
                    else if (!done[s] && pos[s] == kabs) pos[s] = qp;
                }
                float inv = __fdividef(1.0f, piv);
#pragma unroll
                for (int s = 0; s < 4; s++) {
                    if (!done[s]) {
                        float mll = p[s][kk] * inv;
                        p[s][kk] = mll;
#pragma unroll
                        for (int c = kk + 1; c < NB; c++)
                            p[s][c] -= mll * ur[c];
                    }
                }
            }
            __syncwarp();
#pragma unroll
            for (int s = 0; s < 4; s++) {
                if (lane + 32 * s >= k0) {
#pragma unroll
                    for (int c = 0; c < NB; c++)
                        A(pos[s], k0 + c) = p[s][c];
                }
            }
        }
        __syncthreads();   // panel + pivot list visible to all warps

        int base = k0 + NB;
        int m2 = NLU - base;

        if (m2 > 0) {
            // ===== fused: apply row swaps + TRSM, per trailing column ============
            for (int j = base + tid; j < NLU; j += 256) {
#pragma unroll
                for (int k = 0; k < NB; k++) {
                    int qp = s_pivlist[k];
                    int kr = k0 + k;
                    if (qp != kr) {
                        float a0 = A(kr, j), b0 = A(qp, j);
                        A(kr, j) = b0; A(qp, j) = a0;
                    }
                }
                float u[NB];
#pragma unroll
                for (int rr = 0; rr < NB; rr++) {
                    float x = A(k0 + rr, j);
#pragma unroll
                    for (int t = 0; t < NB; t++)
                        if (t < rr) x -= A(k0 + rr, k0 + t) * u[t];
                    u[rr] = x;
                    A(k0 + rr, j) = x;
                }
            }
            __syncthreads();

            // ===== trailing GEMM: adaptive row tiles (no padding waste) ==========
            for (int sa = 0; sa < m2; sa += 64) {
                int rem = m2 - sa;
                int na  = (rem >= 64) ? 4 : ((rem + 15) >> 4);
                for (int sb = 0; sb < m2; sb += 64) {
                    switch (na) {
                        case 4: gemm_tile<4>(k0, base, sa, sb, m2, tx, ty); break;
                        case 3: gemm_tile<3>(k0, base, sa, sb, m2, tx, ty); break;
                        case 2: gemm_tile<2>(k0, base, sa, sb, m2, tx, ty); break;
                        default: gemm_tile<1>(k0, base, sa, sb, m2, tx, ty); break;
                    }
                }
            }
        }
    }

    if (tid == 0) {
        g_sign[cta] = t_sign;
        g_labs[cta] = t_logabs;
    }
}

// ---------------- kernel 4: combine ---------------------------------------------
__global__ void combine_kernel(float* __restrict__ out) {
    int b = blockIdx.x * 256 + threadIdx.x;
    if (b < BATCH) {
        out[b]         = g_sign[2 * b] * g_sign[2 * b + 1];
        out[BATCH + b] = g_logj[b] + g_labs[2 * b] + g_labs[2 * b + 1];
    }
}

// ---------------- launch ---------------------------------------------------------
extern "C" void kernel_launch(void* const* d_in, const int* in_sizes, int n_in,
                              void* d_out, int out_size) {
    const int*   n      = (const int*)d_in[0];
    const float* phi_up = (const float*)d_in[1];
    const float* phi_dn = (const float*)d_in[2];
    const float* v      = (const float*)d_in[3];
    float* out = (float*)d_out;

    const int LU_SMEM = NLU * 129 * (int)sizeof(float);   // 66048 B
    cudaFuncSetAttribute(lu_kernel, cudaFuncAttributeMaxDynamicSharedMemorySize, LU_SMEM);

    idx_kernel<<<BATCH, 256>>>(n);
    jastrow_kernel<<<BATCH / JB, 256>>>(n, v);
    pad_kernel<<<1, 32>>>();                       // keeps lu_kernel at ncu -s 5
    lu_kernel<<<BATCH * 2, 256, LU_SMEM>>>(phi_up, phi_dn);
    combine_kernel<<<(BATCH + 255) / 256, 256>>>(out);
}